// round 1
// baseline (speedup 1.0000x reference)
#include <cuda_runtime.h>
#include <math.h>

// Problem constants
#define BB   128
#define QL   32
#define DL   1024
#define HH   768
#define DIMD 128
#define NEGV (-100000.0f)

// Scratch: normalized Q and its squared norms (written by kernel 1, read by kernel 2)
__device__ float g_Qn[BB * QL * DIMD];
__device__ float g_qsq[BB * QL];

// ---------------------------------------------------------------------------
// Kernel 1: Q projection + L2 normalize.
//   C[4096,128] = Q_emb[4096,768] @ W[128,768]^T, then normalize rows.
// Grid: 32 CTAs (M tiles of 128), 256 threads, 8x8 microtile per thread.
// ---------------------------------------------------------------------------
__global__ __launch_bounds__(256, 1)
void q_proj_kernel(const float* __restrict__ A, const float* __restrict__ W)
{
    __shared__ float As[32 * 132];   // [k][row], padded
    __shared__ float Ws[32 * 132];   // [k][col], padded

    const int tid = threadIdx.x;
    const int tx  = tid & 15;        // 0..15 -> col group
    const int ty  = tid >> 4;        // 0..15 -> row group
    const int m0  = blockIdx.x * 128;

    float acc[8][8];
#pragma unroll
    for (int i = 0; i < 8; i++)
#pragma unroll
        for (int j = 0; j < 8; j++) acc[i][j] = 0.0f;

    for (int kk = 0; kk < HH; kk += 32) {
        __syncthreads();
#pragma unroll
        for (int l = 0; l < 4; l++) {
            int lin = tid + l * 256;          // 0..1023
            int r   = lin >> 3;               // 0..127
            int c4  = lin & 7;                // 0..7 (float4 col)
            float4 v = *(const float4*)(A + (size_t)(m0 + r) * HH + kk + c4 * 4);
            As[(c4 * 4 + 0) * 132 + r] = v.x;
            As[(c4 * 4 + 1) * 132 + r] = v.y;
            As[(c4 * 4 + 2) * 132 + r] = v.z;
            As[(c4 * 4 + 3) * 132 + r] = v.w;
        }
#pragma unroll
        for (int l = 0; l < 4; l++) {
            int lin = tid + l * 256;
            int r   = lin >> 3;
            int c4  = lin & 7;
            float4 v = *(const float4*)(W + (size_t)r * HH + kk + c4 * 4);
            Ws[(c4 * 4 + 0) * 132 + r] = v.x;
            Ws[(c4 * 4 + 1) * 132 + r] = v.y;
            Ws[(c4 * 4 + 2) * 132 + r] = v.z;
            Ws[(c4 * 4 + 3) * 132 + r] = v.w;
        }
        __syncthreads();

#pragma unroll 8
        for (int k = 0; k < 32; k++) {
            float4 a0 = *(const float4*)&As[k * 132 + ty * 8];
            float4 a1 = *(const float4*)&As[k * 132 + ty * 8 + 4];
            float4 w0 = *(const float4*)&Ws[k * 132 + tx * 8];
            float4 w1 = *(const float4*)&Ws[k * 132 + tx * 8 + 4];
            float a[8] = {a0.x, a0.y, a0.z, a0.w, a1.x, a1.y, a1.z, a1.w};
            float w[8] = {w0.x, w0.y, w0.z, w0.w, w1.x, w1.y, w1.z, w1.w};
#pragma unroll
            for (int i = 0; i < 8; i++)
#pragma unroll
                for (int j = 0; j < 8; j++) acc[i][j] = fmaf(a[i], w[j], acc[i][j]);
        }
    }

    // Epilogue: per-row L2 normalize (16 threads with same ty own one row's 128 cols)
#pragma unroll
    for (int i = 0; i < 8; i++) {
        float s = 0.0f;
#pragma unroll
        for (int j = 0; j < 8; j++) s += acc[i][j] * acc[i][j];
#pragma unroll
        for (int o = 8; o >= 1; o >>= 1) s += __shfl_xor_sync(0xffffffffu, s, o, 16);
        float n   = sqrtf(s);
        float inv = 1.0f / fmaxf(n, 1e-12f);
        int   m   = m0 + ty * 8 + i;
#pragma unroll
        for (int j = 0; j < 8; j++) acc[i][j] *= inv;
        float4 v0 = make_float4(acc[i][0], acc[i][1], acc[i][2], acc[i][3]);
        float4 v1 = make_float4(acc[i][4], acc[i][5], acc[i][6], acc[i][7]);
        *(float4*)(g_Qn + (size_t)m * DIMD + tx * 8)     = v0;
        *(float4*)(g_Qn + (size_t)m * DIMD + tx * 8 + 4) = v1;
        if (tx == 0) g_qsq[m] = s * inv * inv;
    }
}

// ---------------------------------------------------------------------------
// Kernel 2: fused D projection + mask + normalize + qd + masked max + sum.
// Grid: 128 CTAs (one per batch), 256 threads. 8 doc-tiles of 128 per CTA.
// ---------------------------------------------------------------------------
#define DS_PAD 132

__global__ __launch_bounds__(256, 1)
void score_kernel(const float* __restrict__ Demb,
                  const int*   __restrict__ ids,
                  const int*   __restrict__ attn,
                  const float* __restrict__ W,
                  float*       __restrict__ out)
{
    extern __shared__ float sm[];
    float* Qs   = sm;                       // 32*128
    float* qsq  = Qs   + QL * DIMD;         // 32
    float* dsq  = qsq  + 32;                // 128
    float* qmax = dsq  + 128;               // 32
    float* Ds   = qmax + 32;                // 128*132 (normalized doc tile)
    float* As   = Ds   + 128 * DS_PAD;      // 32*132
    float* Ws   = As   + 32 * 132;          // 32*132

    const int b   = blockIdx.x;
    const int tid = threadIdx.x;
    const int tx  = tid & 15;
    const int ty  = tid >> 4;
    const int q   = tid >> 3;               // 0..31 query owned in qd phase
    const int g   = tid & 7;                // 0..7 doc group

    // Load normalized Q tile + q_sq
    for (int l = tid; l < QL * DIMD / 4; l += 256)
        ((float4*)Qs)[l] = ((const float4*)(g_Qn + (size_t)b * QL * DIMD))[l];
    if (tid < 32) qsq[tid] = g_qsq[b * QL + tid];

    float lmax = NEGV;   // running max for (q, docs g*16+dd) across all tiles

    for (int t0 = 0; t0 < DL; t0 += 128) {
        float acc[8][8];
#pragma unroll
        for (int i = 0; i < 8; i++)
#pragma unroll
            for (int j = 0; j < 8; j++) acc[i][j] = 0.0f;

        for (int kk = 0; kk < HH; kk += 32) {
            __syncthreads();   // also protects Ds/Qs readers from previous phase
#pragma unroll
            for (int l = 0; l < 4; l++) {
                int lin = tid + l * 256;
                int r   = lin >> 3;
                int c4  = lin & 7;
                float4 v = *(const float4*)(Demb + ((size_t)b * DL + t0 + r) * HH + kk + c4 * 4);
                As[(c4 * 4 + 0) * 132 + r] = v.x;
                As[(c4 * 4 + 1) * 132 + r] = v.y;
                As[(c4 * 4 + 2) * 132 + r] = v.z;
                As[(c4 * 4 + 3) * 132 + r] = v.w;
            }
#pragma unroll
            for (int l = 0; l < 4; l++) {
                int lin = tid + l * 256;
                int r   = lin >> 3;
                int c4  = lin & 7;
                float4 v = *(const float4*)(W + (size_t)r * HH + kk + c4 * 4);
                Ws[(c4 * 4 + 0) * 132 + r] = v.x;
                Ws[(c4 * 4 + 1) * 132 + r] = v.y;
                Ws[(c4 * 4 + 2) * 132 + r] = v.z;
                Ws[(c4 * 4 + 3) * 132 + r] = v.w;
            }
            __syncthreads();

#pragma unroll 8
            for (int k = 0; k < 32; k++) {
                float4 a0 = *(const float4*)&As[k * 132 + ty * 8];
                float4 a1 = *(const float4*)&As[k * 132 + ty * 8 + 4];
                float4 w0 = *(const float4*)&Ws[k * 132 + tx * 8];
                float4 w1 = *(const float4*)&Ws[k * 132 + tx * 8 + 4];
                float a[8] = {a0.x, a0.y, a0.z, a0.w, a1.x, a1.y, a1.z, a1.w};
                float w[8] = {w0.x, w0.y, w0.z, w0.w, w1.x, w1.y, w1.z, w1.w};
#pragma unroll
                for (int i = 0; i < 8; i++)
#pragma unroll
                    for (int j = 0; j < 8; j++) acc[i][j] = fmaf(a[i], w[j], acc[i][j]);
            }
        }

        // Epilogue: ids-mask, per-row normalize, stage into Ds + dsq
#pragma unroll
        for (int i = 0; i < 8; i++) {
            int row = ty * 8 + i;
            int idv = ids[b * DL + t0 + row];
            if (idv == 0) {
#pragma unroll
                for (int j = 0; j < 8; j++) acc[i][j] = 0.0f;
            }
            float s = 0.0f;
#pragma unroll
            for (int j = 0; j < 8; j++) s += acc[i][j] * acc[i][j];
#pragma unroll
            for (int o = 8; o >= 1; o >>= 1) s += __shfl_xor_sync(0xffffffffu, s, o, 16);
            float n   = sqrtf(s);
            float inv = 1.0f / fmaxf(n, 1e-12f);
#pragma unroll
            for (int j = 0; j < 8; j++) acc[i][j] *= inv;
            float4 v0 = make_float4(acc[i][0], acc[i][1], acc[i][2], acc[i][3]);
            float4 v1 = make_float4(acc[i][4], acc[i][5], acc[i][6], acc[i][7]);
            *(float4*)(Ds + row * DS_PAD + tx * 8)     = v0;
            *(float4*)(Ds + row * DS_PAD + tx * 8 + 4) = v1;
            if (tx == 0) dsq[row] = s * inv * inv;
        }
        __syncthreads();

        // qd phase: scores[q][doc] = 2*Q.D - qsq - dsq (or NEG), running max
        const float4* qp = (const float4*)(Qs + q * DIMD);
        const float   myqsq = qsq[q];
#pragma unroll 2
        for (int dd = 0; dd < 16; dd++) {
            int doc = g * 16 + dd;
            const float4* dp = (const float4*)(Ds + doc * DS_PAD);
            float dot = 0.0f;
#pragma unroll
            for (int k4 = 0; k4 < 32; k4++) {
                float4 dv = dp[k4];
                float4 qv = qp[k4];
                dot = fmaf(dv.x, qv.x, dot);
                dot = fmaf(dv.y, qv.y, dot);
                dot = fmaf(dv.z, qv.z, dot);
                dot = fmaf(dv.w, qv.w, dot);
            }
            bool keep = attn[b * DL + t0 + doc] != 0;
            float sc  = keep ? (2.0f * dot - myqsq - dsq[doc]) : NEGV;
            lmax = fmaxf(lmax, sc);
        }
    }

    // Reduce max over the 8 doc-groups per query (lanes q*8+g are contiguous)
#pragma unroll
    for (int o = 4; o >= 1; o >>= 1) lmax = fmaxf(lmax, __shfl_xor_sync(0xffffffffu, lmax, o, 8));
    if (g == 0) qmax[q] = lmax;
    __syncthreads();

    if (tid < 32) {
        float v = qmax[tid];
#pragma unroll
        for (int o = 16; o >= 1; o >>= 1) v += __shfl_xor_sync(0xffffffffu, v, o, 32);
        if (tid == 0) out[b] = v;
    }
}

// ---------------------------------------------------------------------------
extern "C" void kernel_launch(void* const* d_in, const int* in_sizes, int n_in,
                              void* d_out, int out_size)
{
    const float* Qe   = (const float*)d_in[0];  // [128,32,768]
    const float* De   = (const float*)d_in[1];  // [128,1024,768]
    const int*   ids  = (const int*)  d_in[2];  // [128,1024]
    const int*   attn = (const int*)  d_in[3];  // [128,1024]
    const float* W    = (const float*)d_in[4];  // [128,768]
    float*       out  = (float*)d_out;          // [128]

    q_proj_kernel<<<(BB * QL) / 128, 256>>>(Qe, W);

    size_t smem = (size_t)(QL * DIMD + 32 + 128 + 32 + 128 * DS_PAD + 32 * 132 + 32 * 132)
                  * sizeof(float);
    cudaFuncSetAttribute(score_kernel, cudaFuncAttributeMaxDynamicSharedMemorySize,
                         (int)smem);
    score_kernel<<<BB, 256, smem>>>(De, ids, attn, W, out);
}

// round 2
// speedup vs baseline: 1.7253x; 1.7253x over previous
#include <cuda_runtime.h>
#include <math.h>
#include <stdint.h>

// Problem constants
#define BB   128
#define QL   32
#define DL   1024
#define HH   768
#define DIMD 128
#define NEGV (-100000.0f)

// Scratch: normalized Q and its squared norms (written by kernel 1, read by kernel 2)
__device__ float g_Qn[BB * QL * DIMD];
__device__ float g_qsq[BB * QL];

// ---------------------------------------------------------------------------
// Helpers
// ---------------------------------------------------------------------------
__device__ __forceinline__ unsigned smem_u32(const void* p) {
    return (unsigned)__cvta_generic_to_shared(p);
}
__device__ __forceinline__ void cp_async16(unsigned dst, const void* src) {
    asm volatile("cp.async.cg.shared.global [%0], [%1], 16;\n" :: "r"(dst), "l"(src));
}
__device__ __forceinline__ void cp_commit() {
    asm volatile("cp.async.commit_group;\n" ::: "memory");
}
__device__ __forceinline__ void cp_wait1() {
    asm volatile("cp.async.wait_group 1;\n" ::: "memory");
}
__device__ __forceinline__ void cp_wait0() {
    asm volatile("cp.async.wait_group 0;\n" ::: "memory");
}

__device__ __forceinline__ void mma_tf32(float* c, const float* a, const float* bv) {
    asm volatile(
        "mma.sync.aligned.m16n8k8.row.col.f32.tf32.tf32.f32 "
        "{%0,%1,%2,%3}, {%4,%5,%6,%7}, {%8,%9}, {%0,%1,%2,%3};\n"
        : "+f"(c[0]), "+f"(c[1]), "+f"(c[2]), "+f"(c[3])
        : "r"(__float_as_uint(a[0])), "r"(__float_as_uint(a[1])),
          "r"(__float_as_uint(a[2])), "r"(__float_as_uint(a[3])),
          "r"(__float_as_uint(bv[0])), "r"(__float_as_uint(bv[1])));
}

// ---------------------------------------------------------------------------
// Kernel 1: Q projection + L2 normalize (fp32 scalar, known-correct).
// ---------------------------------------------------------------------------
__global__ __launch_bounds__(256, 1)
void q_proj_kernel(const float* __restrict__ A, const float* __restrict__ W)
{
    __shared__ float As[32 * 132];
    __shared__ float Ws[32 * 132];

    const int tid = threadIdx.x;
    const int tx  = tid & 15;
    const int ty  = tid >> 4;
    const int m0  = blockIdx.x * 128;

    float acc[8][8];
#pragma unroll
    for (int i = 0; i < 8; i++)
#pragma unroll
        for (int j = 0; j < 8; j++) acc[i][j] = 0.0f;

    for (int kk = 0; kk < HH; kk += 32) {
        __syncthreads();
#pragma unroll
        for (int l = 0; l < 4; l++) {
            int lin = tid + l * 256;
            int r   = lin >> 3;
            int c4  = lin & 7;
            float4 v = *(const float4*)(A + (size_t)(m0 + r) * HH + kk + c4 * 4);
            As[(c4 * 4 + 0) * 132 + r] = v.x;
            As[(c4 * 4 + 1) * 132 + r] = v.y;
            As[(c4 * 4 + 2) * 132 + r] = v.z;
            As[(c4 * 4 + 3) * 132 + r] = v.w;
        }
#pragma unroll
        for (int l = 0; l < 4; l++) {
            int lin = tid + l * 256;
            int r   = lin >> 3;
            int c4  = lin & 7;
            float4 v = *(const float4*)(W + (size_t)r * HH + kk + c4 * 4);
            Ws[(c4 * 4 + 0) * 132 + r] = v.x;
            Ws[(c4 * 4 + 1) * 132 + r] = v.y;
            Ws[(c4 * 4 + 2) * 132 + r] = v.z;
            Ws[(c4 * 4 + 3) * 132 + r] = v.w;
        }
        __syncthreads();

#pragma unroll 8
        for (int k = 0; k < 32; k++) {
            float4 a0 = *(const float4*)&As[k * 132 + ty * 8];
            float4 a1 = *(const float4*)&As[k * 132 + ty * 8 + 4];
            float4 w0 = *(const float4*)&Ws[k * 132 + tx * 8];
            float4 w1 = *(const float4*)&Ws[k * 132 + tx * 8 + 4];
            float a[8] = {a0.x, a0.y, a0.z, a0.w, a1.x, a1.y, a1.z, a1.w};
            float w[8] = {w0.x, w0.y, w0.z, w0.w, w1.x, w1.y, w1.z, w1.w};
#pragma unroll
            for (int i = 0; i < 8; i++)
#pragma unroll
                for (int j = 0; j < 8; j++) acc[i][j] = fmaf(a[i], w[j], acc[i][j]);
        }
    }

#pragma unroll
    for (int i = 0; i < 8; i++) {
        float s = 0.0f;
#pragma unroll
        for (int j = 0; j < 8; j++) s += acc[i][j] * acc[i][j];
#pragma unroll
        for (int o = 8; o >= 1; o >>= 1) s += __shfl_xor_sync(0xffffffffu, s, o, 16);
        float n   = sqrtf(s);
        float inv = 1.0f / fmaxf(n, 1e-12f);
        int   m   = m0 + ty * 8 + i;
#pragma unroll
        for (int j = 0; j < 8; j++) acc[i][j] *= inv;
        float4 v0 = make_float4(acc[i][0], acc[i][1], acc[i][2], acc[i][3]);
        float4 v1 = make_float4(acc[i][4], acc[i][5], acc[i][6], acc[i][7]);
        *(float4*)(g_Qn + (size_t)m * DIMD + tx * 8)     = v0;
        *(float4*)(g_Qn + (size_t)m * DIMD + tx * 8 + 4) = v1;
        if (tx == 0) g_qsq[m] = s * inv * inv;
    }
}

// ---------------------------------------------------------------------------
// Kernel 2: fused D projection (tf32 mma) + mask + normalize + qd + max + sum.
// Grid: 128 CTAs (one per batch), 256 threads = 8 warps (4 M x 2 N).
// Per doc-tile: C[128,128] = Demb_tile[128,768] x W[128,768]^T via m16n8k8.
// Smem tiles row-major [row][k], k-stage 32, pad to 36, 2-stage cp.async.
// ---------------------------------------------------------------------------
#define KSTG   32
#define APAD   36
#define DS_PAD 132
#define NSTG   (HH / KSTG)   // 24

struct SmemLayout {
    // float offsets into dynamic smem
    // Qs:4096  qsq:32  dsq:128  qmax:32  rs:256  Ds:16896  Ab0/Ab1/Wb0/Wb1: 4608 each
};

__device__ __forceinline__ void load_stage(float* Asm, float* Wsm,
                                           const float* __restrict__ Ag,
                                           const float* __restrict__ Wg,
                                           int tid)
{
#pragma unroll
    for (int l = 0; l < 4; l++) {
        int lin = tid + l * 256;
        int row = lin >> 3;
        int ch  = lin & 7;
        cp_async16(smem_u32(Asm + row * APAD + ch * 4), Ag + (size_t)row * HH + ch * 4);
    }
#pragma unroll
    for (int l = 0; l < 4; l++) {
        int lin = tid + l * 256;
        int row = lin >> 3;
        int ch  = lin & 7;
        cp_async16(smem_u32(Wsm + row * APAD + ch * 4), Wg + (size_t)row * HH + ch * 4);
    }
}

__global__ __launch_bounds__(256, 1)
void score_kernel(const float* __restrict__ Demb,
                  const int*   __restrict__ ids,
                  const int*   __restrict__ attn,
                  const float* __restrict__ W,
                  float*       __restrict__ out)
{
    extern __shared__ float sm[];
    float* Qs   = sm;                        // 32*128 = 4096
    float* qsq  = Qs   + QL * DIMD;          // 32
    float* dsq  = qsq  + 32;                 // 128
    float* qmax = dsq  + 128;                // 32
    float* rs   = qmax + 32;                 // 2*128 = 256
    float* Ds   = rs   + 256;                // 128*132 = 16896
    float* Ab0  = Ds   + 128 * DS_PAD;       // 128*36 = 4608
    float* Ab1  = Ab0  + 128 * APAD;
    float* Wb0  = Ab1  + 128 * APAD;
    float* Wb1  = Wb0  + 128 * APAD;
    float* Abuf[2] = {Ab0, Ab1};
    float* Wbuf[2] = {Wb0, Wb1};

    const int b    = blockIdx.x;
    const int tid  = threadIdx.x;
    const int lane = tid & 31;
    const int warp = tid >> 5;
    const int warpM = warp >> 1;     // 0..3 -> rows warpM*32..+31
    const int warpN = warp & 1;      // 0..1 -> cols warpN*64..+63
    const int gq   = lane >> 2;      // groupID 0..7
    const int tg   = lane & 3;       // threadID_in_group 0..3

    // Load normalized Q tile + q_sq
    for (int l = tid; l < QL * DIMD / 4; l += 256)
        ((float4*)Qs)[l] = ((const float4*)(g_Qn + (size_t)b * QL * DIMD))[l];
    if (tid < 32) qsq[tid] = g_qsq[b * QL + tid];

    float lmax = NEGV;

    for (int t0 = 0; t0 < DL; t0 += 128) {
        float acc[2][8][4];
#pragma unroll
        for (int m = 0; m < 2; m++)
#pragma unroll
            for (int nt = 0; nt < 8; nt++)
#pragma unroll
                for (int r = 0; r < 4; r++) acc[m][nt][r] = 0.0f;

        const float* Agbase = Demb + ((size_t)b * DL + t0) * HH;

        load_stage(Abuf[0], Wbuf[0], Agbase, W, tid);
        cp_commit();

        for (int s = 0; s < NSTG; s++) {
            if (s + 1 < NSTG) {
                load_stage(Abuf[(s + 1) & 1], Wbuf[(s + 1) & 1],
                           Agbase + (s + 1) * KSTG, W + (s + 1) * KSTG, tid);
                cp_commit();
                cp_wait1();
            } else {
                cp_wait0();
            }
            __syncthreads();

            const float* Asm = Abuf[s & 1];
            const float* Wsm = Wbuf[s & 1];
#pragma unroll
            for (int kb = 0; kb < 4; kb++) {
                float afr[2][4];
#pragma unroll
                for (int m = 0; m < 2; m++) {
                    const float* p = Asm + (warpM * 32 + m * 16 + gq) * APAD + kb * 8 + tg;
                    afr[m][0] = p[0];
                    afr[m][1] = p[8 * APAD];
                    afr[m][2] = p[4];
                    afr[m][3] = p[8 * APAD + 4];
                }
                float bfr[8][2];
#pragma unroll
                for (int nt = 0; nt < 8; nt++) {
                    const float* p = Wsm + (warpN * 64 + nt * 8 + gq) * APAD + kb * 8 + tg;
                    bfr[nt][0] = p[0];
                    bfr[nt][1] = p[4];
                }
#pragma unroll
                for (int m = 0; m < 2; m++)
#pragma unroll
                    for (int nt = 0; nt < 8; nt++)
                        mma_tf32(acc[m][nt], afr[m], bfr[nt]);
            }
            __syncthreads();
        }

        // ---- Epilogue: mask, row L2-normalize, stage Ds + dsq ----
        // Thread owns rows: warpM*32 + m*16 + h*8 + gq  (m,h in {0,1})
        // and cols: warpN*64 + nt*8 + tg*2 (+1)
#pragma unroll
        for (int m = 0; m < 2; m++) {
#pragma unroll
            for (int h = 0; h < 2; h++) {
                int row = warpM * 32 + m * 16 + h * 8 + gq;
                bool z  = (ids[b * DL + t0 + row] == 0);
                float s = 0.0f;
#pragma unroll
                for (int nt = 0; nt < 8; nt++) {
                    if (z) { acc[m][nt][h * 2] = 0.0f; acc[m][nt][h * 2 + 1] = 0.0f; }
                    float x = acc[m][nt][h * 2];
                    float y = acc[m][nt][h * 2 + 1];
                    s += x * x + y * y;
                }
                s += __shfl_xor_sync(0xffffffffu, s, 1);
                s += __shfl_xor_sync(0xffffffffu, s, 2);
                if (tg == 0) rs[warpN * 128 + row] = s;
            }
        }
        __syncthreads();

#pragma unroll
        for (int m = 0; m < 2; m++) {
#pragma unroll
            for (int h = 0; h < 2; h++) {
                int row   = warpM * 32 + m * 16 + h * 8 + gq;
                float st  = rs[row] + rs[128 + row];
                float inv = 1.0f / fmaxf(sqrtf(st), 1e-12f);
#pragma unroll
                for (int nt = 0; nt < 8; nt++) {
                    int col = warpN * 64 + nt * 8 + tg * 2;
                    float2 v;
                    v.x = acc[m][nt][h * 2]     * inv;
                    v.y = acc[m][nt][h * 2 + 1] * inv;
                    *(float2*)(Ds + row * DS_PAD + col) = v;
                }
                if (warpN == 0 && tg == 0) dsq[row] = st * inv * inv;
            }
        }
        __syncthreads();

        // ---- qd phase: scores = 2*Q.D - qsq - dsq (or NEG), running max ----
        {
            const int q  = tid >> 3;       // 0..31
            const int dg = tid & 7;        // 0..7
            const float4* qp   = (const float4*)(Qs + q * DIMD);
            const float   myqs = qsq[q];
#pragma unroll 2
            for (int dd = 0; dd < 16; dd++) {
                int doc = dg * 16 + dd;
                const float4* dp = (const float4*)(Ds + doc * DS_PAD);
                float dot = 0.0f;
#pragma unroll
                for (int k4 = 0; k4 < 32; k4++) {
                    float4 dv = dp[k4];
                    float4 qv = qp[k4];
                    dot = fmaf(dv.x, qv.x, dot);
                    dot = fmaf(dv.y, qv.y, dot);
                    dot = fmaf(dv.z, qv.z, dot);
                    dot = fmaf(dv.w, qv.w, dot);
                }
                bool keep = attn[b * DL + t0 + doc] != 0;
                float sc  = keep ? (2.0f * dot - myqs - dsq[doc]) : NEGV;
                lmax = fmaxf(lmax, sc);
            }
        }
        __syncthreads();
    }

    // Reduce max over the 8 doc-groups per query, then sum over queries
#pragma unroll
    for (int o = 4; o >= 1; o >>= 1)
        lmax = fmaxf(lmax, __shfl_xor_sync(0xffffffffu, lmax, o, 8));
    if ((tid & 7) == 0) qmax[tid >> 3] = lmax;
    __syncthreads();

    if (tid < 32) {
        float v = qmax[tid];
#pragma unroll
        for (int o = 16; o >= 1; o >>= 1) v += __shfl_xor_sync(0xffffffffu, v, o, 32);
        if (tid == 0) out[b] = v;
    }
}

// ---------------------------------------------------------------------------
extern "C" void kernel_launch(void* const* d_in, const int* in_sizes, int n_in,
                              void* d_out, int out_size)
{
    const float* Qe   = (const float*)d_in[0];  // [128,32,768]
    const float* De   = (const float*)d_in[1];  // [128,1024,768]
    const int*   ids  = (const int*)  d_in[2];  // [128,1024]
    const int*   attn = (const int*)  d_in[3];  // [128,1024]
    const float* W    = (const float*)d_in[4];  // [128,768]
    float*       out  = (float*)d_out;          // [128]

    q_proj_kernel<<<(BB * QL) / 128, 256>>>(Qe, W);

    size_t smem = (size_t)(QL * DIMD + 32 + 128 + 32 + 256 + 128 * DS_PAD
                           + 4 * 128 * APAD) * sizeof(float);
    cudaFuncSetAttribute(score_kernel, cudaFuncAttributeMaxDynamicSharedMemorySize,
                         (int)smem);
    score_kernel<<<BB, 256, smem>>>(De, ids, attn, W, out);
}

// round 4
// speedup vs baseline: 2.0732x; 1.2017x over previous
#include <cuda_runtime.h>
#include <cuda_bf16.h>
#include <math.h>
#include <stdint.h>

// Problem constants
#define BB   128
#define QL   32
#define DL   1024
#define HH   768
#define DIMD 128
#define NEGV (-100000.0f)
#define DS_PAD 132

// Scratch
__device__ float g_Qn[BB * QL * DIMD];
__device__ float g_qsq[BB * QL];
__device__ __nv_bfloat16 g_Wbf[DIMD * HH];   // bf16 copy of W

// ---------------------------------------------------------------------------
// Helpers (all base-ISA: sm_80+)
// ---------------------------------------------------------------------------
__device__ __forceinline__ unsigned smem_u32(const void* p) {
    return (unsigned)__cvta_generic_to_shared(p);
}
__device__ __forceinline__ void cp_async16(unsigned dst, const void* src) {
    asm volatile("cp.async.cg.shared.global [%0], [%1], 16;\n" :: "r"(dst), "l"(src));
}
__device__ __forceinline__ void cp_commit() {
    asm volatile("cp.async.commit_group;\n" ::: "memory");
}
__device__ __forceinline__ void cp_wait1() {
    asm volatile("cp.async.wait_group 1;\n" ::: "memory");
}
__device__ __forceinline__ void cp_wait0() {
    asm volatile("cp.async.wait_group 0;\n" ::: "memory");
}
__device__ __forceinline__ uint32_t f2bf2(float lo, float hi) {
    uint32_t r;
    asm("cvt.rn.bf16x2.f32 %0, %1, %2;" : "=r"(r) : "f"(hi), "f"(lo));
    return r;
}
__device__ __forceinline__ void ldsm_x4(uint32_t* r, uint32_t addr) {
    asm volatile("ldmatrix.sync.aligned.m8n8.x4.shared.b16 {%0,%1,%2,%3}, [%4];"
                 : "=r"(r[0]), "=r"(r[1]), "=r"(r[2]), "=r"(r[3]) : "r"(addr));
}
__device__ __forceinline__ void sts128(uint32_t addr, uint32_t r0, uint32_t r1,
                                       uint32_t r2, uint32_t r3) {
    asm volatile("st.shared.v4.b32 [%0], {%1,%2,%3,%4};"
                 :: "r"(addr), "r"(r0), "r"(r1), "r"(r2), "r"(r3) : "memory");
}
__device__ __forceinline__ void mma_bf16(float* c, const uint32_t* a, const uint32_t* b) {
    asm volatile(
        "mma.sync.aligned.m16n8k16.row.col.f32.bf16.bf16.f32 "
        "{%0,%1,%2,%3}, {%4,%5,%6,%7}, {%8,%9}, {%0,%1,%2,%3};"
        : "+f"(c[0]), "+f"(c[1]), "+f"(c[2]), "+f"(c[3])
        : "r"(a[0]), "r"(a[1]), "r"(a[2]), "r"(a[3]), "r"(b[0]), "r"(b[1]));
}

// ---------------------------------------------------------------------------
// Kernel 0: W fp32 -> bf16 (96 CTAs x 256 thr, one float4 each)
// ---------------------------------------------------------------------------
__global__ void wconv_kernel(const float* __restrict__ W)
{
    int i = blockIdx.x * 256 + threadIdx.x;          // 24576 float4s
    float4 v = *(const float4*)(W + (size_t)i * 4);
    uint32_t p0 = f2bf2(v.x, v.y);
    uint32_t p1 = f2bf2(v.z, v.w);
    *(uint2*)((char*)g_Wbf + (size_t)i * 8) = make_uint2(p0, p1);
}

// ---------------------------------------------------------------------------
// Kernel 1: Q projection + L2 normalize (fp32 scalar). 128 CTAs, 256 thr.
// ---------------------------------------------------------------------------
__global__ __launch_bounds__(256, 1)
void q_proj_kernel(const float* __restrict__ Qe, const float* __restrict__ W)
{
    __shared__ float As[32 * 33];
    __shared__ float Ws[32 * 132];

    const int b   = blockIdx.x;
    const int tid = threadIdx.x;
    const int tx  = tid & 15;
    const int ty  = tid >> 4;
    const float* A = Qe + (size_t)b * QL * HH;

    float acc[2][8];
#pragma unroll
    for (int i = 0; i < 2; i++)
#pragma unroll
        for (int j = 0; j < 8; j++) acc[i][j] = 0.0f;

    for (int kk = 0; kk < HH; kk += 32) {
        __syncthreads();
        {
            int r  = tid >> 3;
            int c4 = tid & 7;
            float4 v = *(const float4*)(A + (size_t)r * HH + kk + c4 * 4);
            As[(c4 * 4 + 0) * 33 + r] = v.x;
            As[(c4 * 4 + 1) * 33 + r] = v.y;
            As[(c4 * 4 + 2) * 33 + r] = v.z;
            As[(c4 * 4 + 3) * 33 + r] = v.w;
        }
#pragma unroll
        for (int l = 0; l < 4; l++) {
            int lin = tid + l * 256;
            int r   = lin >> 3;
            int c4  = lin & 7;
            float4 v = *(const float4*)(W + (size_t)r * HH + kk + c4 * 4);
            Ws[(c4 * 4 + 0) * 132 + r] = v.x;
            Ws[(c4 * 4 + 1) * 132 + r] = v.y;
            Ws[(c4 * 4 + 2) * 132 + r] = v.z;
            Ws[(c4 * 4 + 3) * 132 + r] = v.w;
        }
        __syncthreads();

#pragma unroll 8
        for (int k = 0; k < 32; k++) {
            float a0 = As[k * 33 + ty * 2];
            float a1 = As[k * 33 + ty * 2 + 1];
            float4 w0 = *(const float4*)&Ws[k * 132 + tx * 8];
            float4 w1 = *(const float4*)&Ws[k * 132 + tx * 8 + 4];
            float w[8] = {w0.x, w0.y, w0.z, w0.w, w1.x, w1.y, w1.z, w1.w};
#pragma unroll
            for (int j = 0; j < 8; j++) {
                acc[0][j] = fmaf(a0, w[j], acc[0][j]);
                acc[1][j] = fmaf(a1, w[j], acc[1][j]);
            }
        }
    }

#pragma unroll
    for (int i = 0; i < 2; i++) {
        float s = 0.0f;
#pragma unroll
        for (int j = 0; j < 8; j++) s += acc[i][j] * acc[i][j];
#pragma unroll
        for (int o = 8; o >= 1; o >>= 1) s += __shfl_xor_sync(0xffffffffu, s, o, 16);
        float inv = 1.0f / fmaxf(sqrtf(s), 1e-12f);
        int   m   = ty * 2 + i;
#pragma unroll
        for (int j = 0; j < 8; j++) acc[i][j] *= inv;
        float4 v0 = make_float4(acc[i][0], acc[i][1], acc[i][2], acc[i][3]);
        float4 v1 = make_float4(acc[i][4], acc[i][5], acc[i][6], acc[i][7]);
        *(float4*)(g_Qn + ((size_t)b * QL + m) * DIMD + tx * 8)     = v0;
        *(float4*)(g_Qn + ((size_t)b * QL + m) * DIMD + tx * 8 + 4) = v1;
        if (tx == 0) g_qsq[b * QL + m] = s * inv * inv;
    }
}

// ---------------------------------------------------------------------------
// Kernel 2: fused D projection (bf16 mma + ldmatrix) + mask + normalize
//           + qd + masked max + sum.  128 CTAs (one batch), 512 threads.
//
// SMEM (bytes):
//   Qs    0       16384   (32x128 f32)
//   Ds    16384   67584   (128x132 f32, normalized doc tile)
//   rs    83968   2048    (4x128 f32 partial norms)
//   dsq   86016   512
//   qmax  86528   128
//   A     87040   18432   (128 rows x 72 bf16; stride 144B, 64 data + 8 pad)
//   W0    105472  18432
//   W1    123904  18432
//   total 142336
// ---------------------------------------------------------------------------
#define SM_QS    0
#define SM_DS    16384
#define SM_RS    83968
#define SM_DSQ   86016
#define SM_QMAX  86528
#define SM_A     87040
#define SM_W0    105472
#define SM_W1    123904
#define SM_TOTAL 142336

#define RSTRIDE 144          // bytes per smem row (64 bf16 + 8 pad)
#define KC      64           // k per chunk (elements)
#define NCHUNK  (HH / KC)    // 12

__global__ __launch_bounds__(512, 1)
void score_kernel(const float* __restrict__ Demb,
                  const int*   __restrict__ ids,
                  const int*   __restrict__ attn,
                  float*       __restrict__ out)
{
    extern __shared__ char smc[];
    float* Qs   = (float*)(smc + SM_QS);
    float* Ds   = (float*)(smc + SM_DS);
    float* rs   = (float*)(smc + SM_RS);
    float* dsq  = (float*)(smc + SM_DSQ);
    float* qmax = (float*)(smc + SM_QMAX);

    const uint32_t base = smem_u32(smc);

    const int b    = blockIdx.x;
    const int tid  = threadIdx.x;
    const int lane = tid & 31;
    const int warp = tid >> 5;
    const int warpM = warp >> 2;       // 0..3 -> rows warpM*32..+31
    const int warpN = warp & 3;        // 0..3 -> cols warpN*32..+31
    const int g    = lane >> 2;        // 0..7
    const int t    = lane & 3;         // 0..3

    // Staging thread coords (2 iters of 512): row = lin>>3 (0..127), c8 = lin&7
    const int r0 = tid >> 3;           // rows r0, r0+64
    const int c8 = tid & 7;

    // ldmatrix per-lane base offsets
    const uint32_t aoff = (uint32_t)(warpM * 32 + (lane & 15)) * RSTRIDE
                        + ((lane >> 4) & 1) * 16;
    const uint32_t boff = (uint32_t)(warpN * 32 + ((lane >> 4) & 1) * 8 + (lane & 7)) * RSTRIDE
                        + ((lane >> 3) & 1) * 16;
    const uint32_t Au  = base + SM_A  + aoff;
    const uint32_t Wu0 = base + SM_W0 + boff;
    const uint32_t Wu1 = base + SM_W1 + boff;

    // Load normalized Q tile + q_sq
    for (int l = tid; l < QL * DIMD / 4; l += 512)
        ((float4*)Qs)[l] = ((const float4*)(g_Qn + (size_t)b * QL * DIMD))[l];
    if (tid < 32) qsq_load: ;
    __shared__ float qsq[QL];
    if (tid < 32) qsq[tid] = g_qsq[b * QL + tid];

    float lmax = NEGV;

    for (int t0 = 0; t0 < DL; t0 += 128) {
        const float* Ag = Demb + ((size_t)b * DL + t0) * HH;

        float acc[2][4][4];
#pragma unroll
        for (int m = 0; m < 2; m++)
#pragma unroll
            for (int n = 0; n < 4; n++)
#pragma unroll
                for (int r = 0; r < 4; r++) acc[m][n][r] = 0.0f;

        // Prologue: LDG chunk0 (A), cp.async W chunk0
        float4 ra[2][2];
#pragma unroll
        for (int l = 0; l < 2; l++) {
            const float* p = Ag + (size_t)(r0 + l * 64) * HH + c8 * 8;
            ra[l][0] = *(const float4*)(p);
            ra[l][1] = *(const float4*)(p + 4);
        }
#pragma unroll
        for (int l = 0; l < 2; l++) {
            int lin = tid + l * 512;
            int wr  = lin >> 3;
            int wc  = lin & 7;
            cp_async16(base + SM_W0 + wr * RSTRIDE + wc * 16,
                       (const char*)g_Wbf + ((size_t)wr * HH) * 2 + wc * 16);
        }
        cp_commit();

        for (int s = 0; s < NCHUNK; s++) {
            __syncthreads();   // A buffer free (previous chunk's ldmatrix done)

            // STS: convert staged fp32 regs -> bf16 smem
#pragma unroll
            for (int l = 0; l < 2; l++) {
                uint32_t addr = base + SM_A + (uint32_t)(r0 + l * 64) * RSTRIDE + c8 * 16;
                sts128(addr,
                       f2bf2(ra[l][0].x, ra[l][0].y), f2bf2(ra[l][0].z, ra[l][0].w),
                       f2bf2(ra[l][1].x, ra[l][1].y), f2bf2(ra[l][1].z, ra[l][1].w));
            }

            if (s < NCHUNK - 1) {
                // Prefetch next A chunk into registers (overlaps MMA below)
#pragma unroll
                for (int l = 0; l < 2; l++) {
                    const float* p = Ag + (size_t)(r0 + l * 64) * HH + (s + 1) * KC + c8 * 8;
                    ra[l][0] = *(const float4*)(p);
                    ra[l][1] = *(const float4*)(p + 4);
                }
                // Prefetch next W chunk
                uint32_t wdst = base + ((s + 1) & 1 ? SM_W1 : SM_W0);
#pragma unroll
                for (int l = 0; l < 2; l++) {
                    int lin = tid + l * 512;
                    int wr  = lin >> 3;
                    int wc  = lin & 7;
                    cp_async16(wdst + wr * RSTRIDE + wc * 16,
                               (const char*)g_Wbf + ((size_t)wr * HH + (s + 1) * KC) * 2 + wc * 16);
                }
                cp_commit();
                cp_wait1();
            } else {
                cp_wait0();
            }
            __syncthreads();   // A staged + W chunk s ready

            const uint32_t wb = (s & 1) ? Wu1 : Wu0;
#pragma unroll
            for (int kb = 0; kb < 4; kb++) {
                uint32_t a0[4], a1[4], b0[4], b1[4];
                ldsm_x4(a0, Au + kb * 32);
                ldsm_x4(a1, Au + 16 * RSTRIDE + kb * 32);
                ldsm_x4(b0, wb + kb * 32);
                ldsm_x4(b1, wb + 16 * RSTRIDE + kb * 32);
                mma_bf16(acc[0][0], a0, b0);
                mma_bf16(acc[0][1], a0, b0 + 2);
                mma_bf16(acc[0][2], a0, b1);
                mma_bf16(acc[0][3], a0, b1 + 2);
                mma_bf16(acc[1][0], a1, b0);
                mma_bf16(acc[1][1], a1, b0 + 2);
                mma_bf16(acc[1][2], a1, b1);
                mma_bf16(acc[1][3], a1, b1 + 2);
            }
        }

        // ---- Epilogue: mask, row L2-normalize (4-warp partials), stage Ds ----
#pragma unroll
        for (int m = 0; m < 2; m++) {
#pragma unroll
            for (int h = 0; h < 2; h++) {
                int row = warpM * 32 + m * 16 + h * 8 + g;
                bool z  = (ids[b * DL + t0 + row] == 0);
                float s = 0.0f;
#pragma unroll
                for (int n = 0; n < 4; n++) {
                    if (z) { acc[m][n][h * 2] = 0.0f; acc[m][n][h * 2 + 1] = 0.0f; }
                    float x = acc[m][n][h * 2];
                    float y = acc[m][n][h * 2 + 1];
                    s += x * x + y * y;
                }
                s += __shfl_xor_sync(0xffffffffu, s, 1, 4);
                s += __shfl_xor_sync(0xffffffffu, s, 2, 4);
                if (t == 0) rs[warpN * 128 + row] = s;
            }
        }
        __syncthreads();

#pragma unroll
        for (int m = 0; m < 2; m++) {
#pragma unroll
            for (int h = 0; h < 2; h++) {
                int row   = warpM * 32 + m * 16 + h * 8 + g;
                float st  = rs[row] + rs[128 + row] + rs[256 + row] + rs[384 + row];
                float inv = 1.0f / fmaxf(sqrtf(st), 1e-12f);
#pragma unroll
                for (int n = 0; n < 4; n++) {
                    int col = warpN * 32 + n * 8 + t * 2;
                    float2 v;
                    v.x = acc[m][n][h * 2]     * inv;
                    v.y = acc[m][n][h * 2 + 1] * inv;
                    *(float2*)(Ds + row * DS_PAD + col) = v;
                }
                if (warpN == 0 && t == 0) dsq[row] = st * inv * inv;
            }
        }
        __syncthreads();

        // ---- qd phase: 512 threads; scores = 2 Q.D - qsq - dsq, running max
        {
            const int q  = tid >> 4;       // 0..31
            const int dg = tid & 15;       // 0..15 -> 8 docs each
            const float4* qp   = (const float4*)(Qs + q * DIMD);
            const float   myqs = qsq[q];
#pragma unroll 2
            for (int dd = 0; dd < 8; dd++) {
                int doc = dg * 8 + dd;
                const float4* dp = (const float4*)(Ds + doc * DS_PAD);
                float dot = 0.0f;
#pragma unroll
                for (int k4 = 0; k4 < 32; k4++) {
                    float4 dv = dp[k4];
                    float4 qv = qp[k4];
                    dot = fmaf(dv.x, qv.x, dot);
                    dot = fmaf(dv.y, qv.y, dot);
                    dot = fmaf(dv.z, qv.z, dot);
                    dot = fmaf(dv.w, qv.w, dot);
                }
                bool keep = attn[b * DL + t0 + doc] != 0;
                float sc  = keep ? (2.0f * dot - myqs - dsq[doc]) : NEGV;
                lmax = fmaxf(lmax, sc);
            }
        }
        __syncthreads();
    }

    // Reduce max over the 16 doc-groups per query, then sum over queries
#pragma unroll
    for (int o = 8; o >= 1; o >>= 1)
        lmax = fmaxf(lmax, __shfl_xor_sync(0xffffffffu, lmax, o, 16));
    if ((tid & 15) == 0) qmax[tid >> 4] = lmax;
    __syncthreads();

    if (tid < 32) {
        float v = qmax[tid];
#pragma unroll
        for (int o = 16; o >= 1; o >>= 1) v += __shfl_xor_sync(0xffffffffu, v, o, 32);
        if (tid == 0) out[b] = v;
    }
}

// ---------------------------------------------------------------------------
extern "C" void kernel_launch(void* const* d_in, const int* in_sizes, int n_in,
                              void* d_out, int out_size)
{
    const float* Qe   = (const float*)d_in[0];  // [128,32,768]
    const float* De   = (const float*)d_in[1];  // [128,1024,768]
    const int*   ids  = (const int*)  d_in[2];  // [128,1024]
    const int*   attn = (const int*)  d_in[3];  // [128,1024]
    const float* W    = (const float*)d_in[4];  // [128,768]
    float*       out  = (float*)d_out;          // [128]

    wconv_kernel<<<(DIMD * HH) / (256 * 4), 256>>>(W);
    q_proj_kernel<<<BB, 256>>>(Qe, W);

    cudaFuncSetAttribute(score_kernel, cudaFuncAttributeMaxDynamicSharedMemorySize,
                         SM_TOTAL);
    score_kernel<<<BB, 512, SM_TOTAL>>>(De, ids, attn, out);
}

// round 6
// speedup vs baseline: 5.3121x; 2.5622x over previous
#include <cuda_runtime.h>
#include <cuda_bf16.h>
#include <math.h>
#include <stdint.h>

// Problem constants
#define BB   128
#define QL   32
#define DL   1024
#define HH   768
#define DIMD 128
#define NEGV (-100000.0f)

// Scratch
__device__ float g_Qn[BB * QL * DIMD];
__device__ float g_qsq[BB * QL];
__device__ __nv_bfloat16 g_Wbf[DIMD * HH];   // bf16 copy of W

// ---------------------------------------------------------------------------
// Helpers (base-ISA sm_80+)
// ---------------------------------------------------------------------------
__device__ __forceinline__ unsigned smem_u32(const void* p) {
    return (unsigned)__cvta_generic_to_shared(p);
}
__device__ __forceinline__ void cp_async16(unsigned dst, const void* src) {
    asm volatile("cp.async.cg.shared.global [%0], [%1], 16;\n" :: "r"(dst), "l"(src));
}
__device__ __forceinline__ void cp_commit() {
    asm volatile("cp.async.commit_group;\n" ::: "memory");
}
__device__ __forceinline__ void cp_wait1() {
    asm volatile("cp.async.wait_group 1;\n" ::: "memory");
}
__device__ __forceinline__ void cp_wait0() {
    asm volatile("cp.async.wait_group 0;\n" ::: "memory");
}
__device__ __forceinline__ uint32_t f2bf2(float lo, float hi) {
    uint32_t r;
    asm("cvt.rn.bf16x2.f32 %0, %1, %2;" : "=r"(r) : "f"(hi), "f"(lo));
    return r;
}
__device__ __forceinline__ void ldsm_x4(uint32_t* r, uint32_t addr) {
    asm volatile("ldmatrix.sync.aligned.m8n8.x4.shared.b16 {%0,%1,%2,%3}, [%4];"
                 : "=r"(r[0]), "=r"(r[1]), "=r"(r[2]), "=r"(r[3]) : "r"(addr));
}
__device__ __forceinline__ void sts128(uint32_t addr, uint32_t r0, uint32_t r1,
                                       uint32_t r2, uint32_t r3) {
    asm volatile("st.shared.v4.b32 [%0], {%1,%2,%3,%4};"
                 :: "r"(addr), "r"(r0), "r"(r1), "r"(r2), "r"(r3) : "memory");
}
__device__ __forceinline__ void sts32(uint32_t addr, uint32_t r0) {
    asm volatile("st.shared.b32 [%0], %1;" :: "r"(addr), "r"(r0) : "memory");
}
__device__ __forceinline__ void mma_bf16(float* c, const uint32_t* a, const uint32_t* b) {
    asm volatile(
        "mma.sync.aligned.m16n8k16.row.col.f32.bf16.bf16.f32 "
        "{%0,%1,%2,%3}, {%4,%5,%6,%7}, {%8,%9}, {%0,%1,%2,%3};"
        : "+f"(c[0]), "+f"(c[1]), "+f"(c[2]), "+f"(c[3])
        : "r"(a[0]), "r"(a[1]), "r"(a[2]), "r"(a[3]), "r"(b[0]), "r"(b[1]));
}

// ---------------------------------------------------------------------------
// Kernel 0: W fp32 -> bf16
// ---------------------------------------------------------------------------
__global__ void wconv_kernel(const float* __restrict__ W)
{
    int i = blockIdx.x * 256 + threadIdx.x;
    float4 v = *(const float4*)(W + (size_t)i * 4);
    *(uint2*)((char*)g_Wbf + (size_t)i * 8) = make_uint2(f2bf2(v.x, v.y), f2bf2(v.z, v.w));
}

// ---------------------------------------------------------------------------
// Kernel 1: Q projection + L2 normalize (fp32). 128 CTAs, 256 thr.
// ---------------------------------------------------------------------------
__global__ __launch_bounds__(256, 1)
void q_proj_kernel(const float* __restrict__ Qe, const float* __restrict__ W)
{
    __shared__ float As[32 * 33];
    __shared__ float Ws[32 * 132];

    const int b   = blockIdx.x;
    const int tid = threadIdx.x;
    const int tx  = tid & 15;
    const int ty  = tid >> 4;
    const float* A = Qe + (size_t)b * QL * HH;

    float acc[2][8];
#pragma unroll
    for (int i = 0; i < 2; i++)
#pragma unroll
        for (int j = 0; j < 8; j++) acc[i][j] = 0.0f;

    for (int kk = 0; kk < HH; kk += 32) {
        __syncthreads();
        {
            int r  = tid >> 3;
            int c4 = tid & 7;
            float4 v = *(const float4*)(A + (size_t)r * HH + kk + c4 * 4);
            As[(c4 * 4 + 0) * 33 + r] = v.x;
            As[(c4 * 4 + 1) * 33 + r] = v.y;
            As[(c4 * 4 + 2) * 33 + r] = v.z;
            As[(c4 * 4 + 3) * 33 + r] = v.w;
        }
#pragma unroll
        for (int l = 0; l < 4; l++) {
            int lin = tid + l * 256;
            int r   = lin >> 3;
            int c4  = lin & 7;
            float4 v = *(const float4*)(W + (size_t)r * HH + kk + c4 * 4);
            Ws[(c4 * 4 + 0) * 132 + r] = v.x;
            Ws[(c4 * 4 + 1) * 132 + r] = v.y;
            Ws[(c4 * 4 + 2) * 132 + r] = v.z;
            Ws[(c4 * 4 + 3) * 132 + r] = v.w;
        }
        __syncthreads();

#pragma unroll 8
        for (int k = 0; k < 32; k++) {
            float a0 = As[k * 33 + ty * 2];
            float a1 = As[k * 33 + ty * 2 + 1];
            float4 w0 = *(const float4*)&Ws[k * 132 + tx * 8];
            float4 w1 = *(const float4*)&Ws[k * 132 + tx * 8 + 4];
            float w[8] = {w0.x, w0.y, w0.z, w0.w, w1.x, w1.y, w1.z, w1.w};
#pragma unroll
            for (int j = 0; j < 8; j++) {
                acc[0][j] = fmaf(a0, w[j], acc[0][j]);
                acc[1][j] = fmaf(a1, w[j], acc[1][j]);
            }
        }
    }

#pragma unroll
    for (int i = 0; i < 2; i++) {
        float s = 0.0f;
#pragma unroll
        for (int j = 0; j < 8; j++) s += acc[i][j] * acc[i][j];
#pragma unroll
        for (int o = 8; o >= 1; o >>= 1) s += __shfl_xor_sync(0xffffffffu, s, o, 16);
        float inv = 1.0f / fmaxf(sqrtf(s), 1e-12f);
        int   m   = ty * 2 + i;
#pragma unroll
        for (int j = 0; j < 8; j++) acc[i][j] *= inv;
        *(float4*)(g_Qn + ((size_t)b * QL + m) * DIMD + tx * 8) =
            make_float4(acc[i][0], acc[i][1], acc[i][2], acc[i][3]);
        *(float4*)(g_Qn + ((size_t)b * QL + m) * DIMD + tx * 8 + 4) =
            make_float4(acc[i][4], acc[i][5], acc[i][6], acc[i][7]);
        if (tx == 0) g_qsq[b * QL + m] = s * inv * inv;
    }
}

// ---------------------------------------------------------------------------
// Kernel 2: fused D projection (bf16 mma) + mask + normalize + MMA scoring.
// 128 CTAs (one batch), 512 threads.
//
// SMEM bytes:
//   Qbf   0       8704    (32 x 128 bf16, row stride 272)
//   Dbf   8704    34816   (128 x 128 bf16, row stride 272)
//   A0    43520   18432   (128 x 64 bf16, row stride 144)
//   A1    61952   18432
//   W0    80384   18432
//   W1    98816   18432
//   W2    117248  18432
//   rs    135680  2048    (4 x 128 f32)
//   dsq   137728  512
//   qsq   138240  128
//   qpart 138368  1024    (32 x 8 f32)
//   total 139392
// ---------------------------------------------------------------------------
#define SM_QBF   0
#define SM_DBF   8704
#define SM_A0    43520
#define SM_A1    61952
#define SM_W0    80384
#define SM_W1    98816
#define SM_W2    117248
#define SM_RS    135680
#define SM_DSQ   137728
#define SM_QSQ   138240
#define SM_QPART 138368
#define SM_TOTAL 139392

#define RSTRIDE 144          // A/W smem row stride (64 bf16 + pad)
#define QSTR    272          // Qbf/Dbf row stride (128 bf16 + pad)
#define KC      64
#define NCHUNK  (HH / KC)    // 12

__global__ __launch_bounds__(512, 1)
void score_kernel(const float* __restrict__ Demb,
                  const int*   __restrict__ ids,
                  const int*   __restrict__ attn,
                  float*       __restrict__ out)
{
    extern __shared__ char smc[];
    float* rs    = (float*)(smc + SM_RS);
    float* dsq   = (float*)(smc + SM_DSQ);
    float* qsq   = (float*)(smc + SM_QSQ);
    float* qpart = (float*)(smc + SM_QPART);

    const uint32_t base = smem_u32(smc);

    const int b    = blockIdx.x;
    const int tid  = threadIdx.x;
    const int lane = tid & 31;
    const int warp = tid >> 5;
    const int warpM = warp >> 2;       // 0..3 -> rows warpM*32..+31
    const int warpN = warp & 3;        // 0..3 -> cols warpN*32..+31
    const int g    = lane >> 2;        // 0..7
    const int t    = lane & 3;         // 0..3

    // Staging coords
    const int r0 = tid >> 3;           // rows r0, r0+64
    const int c8 = tid & 7;

    // Main-GEMM ldmatrix offsets
    const uint32_t aoff = (uint32_t)(warpM * 32 + (lane & 15)) * RSTRIDE
                        + ((lane >> 4) & 1) * 16;
    const uint32_t boff = (uint32_t)(warpN * 32 + ((lane >> 4) & 1) * 8 + (lane & 7)) * RSTRIDE
                        + ((lane >> 3) & 1) * 16;
    const uint32_t Au[2] = {base + SM_A0 + aoff, base + SM_A1 + aoff};
    const uint32_t Wu[3] = {base + SM_W0 + boff, base + SM_W1 + boff, base + SM_W2 + boff};
    const uint32_t Wdst[3] = {base + SM_W0, base + SM_W1, base + SM_W2};

    // Score-GEMM offsets: each warp does m16 x two n8 tiles (n0 and n0+64)
    const int mq = (warp & 1) * 16;
    const int n0 = (warp >> 1) * 8;    // 0..56; second tile at n0+64
    const uint32_t qa = base + SM_QBF + (uint32_t)(mq + (lane & 15)) * QSTR
                      + ((lane >> 4) & 1) * 16;
    const uint32_t da0 = base + SM_DBF + (uint32_t)(n0 + (lane & 7)) * QSTR
                       + ((lane >> 3) & 3) * 16;
    const uint32_t da1 = da0 + 64 * QSTR;

    // Stage Qbf (fp32 g_Qn -> bf16 smem) + qsq
    if (tid < 256) {
        int row = tid >> 3, seg = tid & 7;     // 16 floats per seg
        const float* p = g_Qn + ((size_t)b * QL + row) * DIMD + seg * 16;
        float4 v0 = *(const float4*)(p);
        float4 v1 = *(const float4*)(p + 4);
        float4 v2 = *(const float4*)(p + 8);
        float4 v3 = *(const float4*)(p + 12);
        uint32_t addr = base + SM_QBF + row * QSTR + seg * 32;
        sts128(addr,      f2bf2(v0.x, v0.y), f2bf2(v0.z, v0.w),
                          f2bf2(v1.x, v1.y), f2bf2(v1.z, v1.w));
        sts128(addr + 16, f2bf2(v2.x, v2.y), f2bf2(v2.z, v2.w),
                          f2bf2(v3.x, v3.y), f2bf2(v3.z, v3.w));
    }
    if (tid < 32) qsq[tid] = g_qsq[b * QL + tid];

    float lm0 = NEGV, lm1 = NEGV;      // running max for query rows mq+g, mq+g+8

    for (int t0 = 0; t0 < DL; t0 += 128) {
        const float* Ag = Demb + ((size_t)b * DL + t0) * HH;

        float acc[2][4][4];
#pragma unroll
        for (int m = 0; m < 2; m++)
#pragma unroll
            for (int n = 0; n < 4; n++)
#pragma unroll
                for (int r = 0; r < 4; r++) acc[m][n][r] = 0.0f;

        // Prologue: LDG A chunk0 -> regs; cp.async W chunk0 -> W0
        float4 ra[2][2];
#pragma unroll
        for (int l = 0; l < 2; l++) {
            const float* p = Ag + (size_t)(r0 + l * 64) * HH + c8 * 8;
            ra[l][0] = *(const float4*)(p);
            ra[l][1] = *(const float4*)(p + 4);
        }
#pragma unroll
        for (int l = 0; l < 2; l++) {
            int lin = tid + l * 512;
            int wr  = lin >> 3;
            int wc  = lin & 7;
            cp_async16(Wdst[0] + wr * RSTRIDE + wc * 16,
                       (const char*)g_Wbf + ((size_t)wr * HH) * 2 + wc * 16);
        }
        cp_commit();

        for (int s = 0; s < NCHUNK; s++) {
            const uint32_t abuf = base + ((s & 1) ? SM_A1 : SM_A0);
            // STS chunk s A (regs -> bf16 smem)
#pragma unroll
            for (int l = 0; l < 2; l++) {
                uint32_t addr = abuf + (uint32_t)(r0 + l * 64) * RSTRIDE + c8 * 16;
                sts128(addr,
                       f2bf2(ra[l][0].x, ra[l][0].y), f2bf2(ra[l][0].z, ra[l][0].w),
                       f2bf2(ra[l][1].x, ra[l][1].y), f2bf2(ra[l][1].z, ra[l][1].w));
            }

            if (s < NCHUNK - 1) {
#pragma unroll
                for (int l = 0; l < 2; l++) {
                    const float* p = Ag + (size_t)(r0 + l * 64) * HH + (s + 1) * KC + c8 * 8;
                    ra[l][0] = *(const float4*)(p);
                    ra[l][1] = *(const float4*)(p + 4);
                }
                uint32_t wdst = Wdst[(s + 1) % 3];
#pragma unroll
                for (int l = 0; l < 2; l++) {
                    int lin = tid + l * 512;
                    int wr  = lin >> 3;
                    int wc  = lin & 7;
                    cp_async16(wdst + wr * RSTRIDE + wc * 16,
                               (const char*)g_Wbf + ((size_t)wr * HH + (s + 1) * KC) * 2 + wc * 16);
                }
                cp_commit();
                cp_wait1();
            } else {
                cp_wait0();
            }
            __syncthreads();

            const uint32_t au = Au[s & 1];
            const uint32_t wb = Wu[s % 3];
#pragma unroll
            for (int kb = 0; kb < 4; kb++) {
                uint32_t a0[4], a1[4], b0[4], b1[4];
                ldsm_x4(a0, au + kb * 32);
                ldsm_x4(a1, au + 16 * RSTRIDE + kb * 32);
                ldsm_x4(b0, wb + kb * 32);
                ldsm_x4(b1, wb + 16 * RSTRIDE + kb * 32);
                mma_bf16(acc[0][0], a0, b0);
                mma_bf16(acc[0][1], a0, b0 + 2);
                mma_bf16(acc[0][2], a0, b1);
                mma_bf16(acc[0][3], a0, b1 + 2);
                mma_bf16(acc[1][0], a1, b0);
                mma_bf16(acc[1][1], a1, b0 + 2);
                mma_bf16(acc[1][2], a1, b1);
                mma_bf16(acc[1][3], a1, b1 + 2);
            }
        }

        // ---- Epilogue: mask, row-norm partials ----
#pragma unroll
        for (int m = 0; m < 2; m++) {
#pragma unroll
            for (int h = 0; h < 2; h++) {
                int row = warpM * 32 + m * 16 + h * 8 + g;
                bool z  = (ids[b * DL + t0 + row] == 0);
                float s = 0.0f;
#pragma unroll
                for (int n = 0; n < 4; n++) {
                    if (z) { acc[m][n][h * 2] = 0.0f; acc[m][n][h * 2 + 1] = 0.0f; }
                    float x = acc[m][n][h * 2];
                    float y = acc[m][n][h * 2 + 1];
                    s += x * x + y * y;
                }
                s += __shfl_xor_sync(0xffffffffu, s, 1, 4);
                s += __shfl_xor_sync(0xffffffffu, s, 2, 4);
                if (t == 0) rs[warpN * 128 + row] = s;
            }
        }
        __syncthreads();

        // ---- Normalize -> bf16 Dbf + dsq ----
#pragma unroll
        for (int m = 0; m < 2; m++) {
#pragma unroll
            for (int h = 0; h < 2; h++) {
                int row   = warpM * 32 + m * 16 + h * 8 + g;
                float st  = rs[row] + rs[128 + row] + rs[256 + row] + rs[384 + row];
                float inv = 1.0f / fmaxf(sqrtf(st), 1e-12f);
#pragma unroll
                for (int n = 0; n < 4; n++) {
                    int col = warpN * 32 + n * 8 + t * 2;
                    uint32_t pk = f2bf2(acc[m][n][h * 2] * inv, acc[m][n][h * 2 + 1] * inv);
                    sts32(base + SM_DBF + (uint32_t)row * QSTR + col * 2, pk);
                }
                if (warpN == 0 && t == 0) dsq[row] = st * inv * inv;
            }
        }
        __syncthreads();

        // ---- Score GEMM: S = Q . D^T, two n8 tiles per warp (n0, n0+64) ----
        {
            const float q0 = qsq[mq + g], q1 = qsq[mq + g + 8];
#pragma unroll
            for (int half = 0; half < 2; half++) {
                const uint32_t da = half ? da1 : da0;
                float sacc[4] = {0.0f, 0.0f, 0.0f, 0.0f};
#pragma unroll
                for (int kb = 0; kb < 8; kb += 2) {
                    uint32_t aA[4], aB[4], bb[4];
                    ldsm_x4(aA, qa + kb * 32);
                    ldsm_x4(aB, qa + (kb + 1) * 32);
                    ldsm_x4(bb, da + kb * 32);
                    mma_bf16(sacc, aA, bb);
                    mma_bf16(sacc, aB, bb + 2);
                }
                const int col0 = n0 + half * 64 + t * 2;
                const int col1 = col0 + 1;
                const bool k0  = attn[b * DL + t0 + col0] != 0;
                const bool k1  = attn[b * DL + t0 + col1] != 0;
                const float d0 = dsq[col0], d1 = dsq[col1];
                float s00 = k0 ? (2.0f * sacc[0] - q0 - d0) : NEGV;
                float s01 = k1 ? (2.0f * sacc[1] - q0 - d1) : NEGV;
                float s10 = k0 ? (2.0f * sacc[2] - q1 - d0) : NEGV;
                float s11 = k1 ? (2.0f * sacc[3] - q1 - d1) : NEGV;
                lm0 = fmaxf(lm0, fmaxf(s00, s01));
                lm1 = fmaxf(lm1, fmaxf(s10, s11));
            }
        }
        __syncthreads();   // Dbf/rs reuse next tile
    }

    // Reduce lm over t (4 lanes), write per-warp partials
    lm0 = fmaxf(lm0, __shfl_xor_sync(0xffffffffu, lm0, 1));
    lm0 = fmaxf(lm0, __shfl_xor_sync(0xffffffffu, lm0, 2));
    lm1 = fmaxf(lm1, __shfl_xor_sync(0xffffffffu, lm1, 1));
    lm1 = fmaxf(lm1, __shfl_xor_sync(0xffffffffu, lm1, 2));
    if (t == 0) {
        int wc = warp >> 1;
        qpart[(mq + g) * 8 + wc]     = lm0;
        qpart[(mq + g + 8) * 8 + wc] = lm1;
    }
    __syncthreads();

    if (tid < 32) {
        float v = NEGV;
#pragma unroll
        for (int j = 0; j < 8; j++) v = fmaxf(v, qpart[tid * 8 + j]);
#pragma unroll
        for (int o = 16; o >= 1; o >>= 1) v += __shfl_xor_sync(0xffffffffu, v, o, 32);
        if (tid == 0) out[b] = v;
    }
}

// ---------------------------------------------------------------------------
extern "C" void kernel_launch(void* const* d_in, const int* in_sizes, int n_in,
                              void* d_out, int out_size)
{
    const float* Qe   = (const float*)d_in[0];  // [128,32,768]
    const float* De   = (const float*)d_in[1];  // [128,1024,768]
    const int*   ids  = (const int*)  d_in[2];  // [128,1024]
    const int*   attn = (const int*)  d_in[3];  // [128,1024]
    const float* W    = (const float*)d_in[4];  // [128,768]
    float*       out  = (float*)d_out;          // [128]

    wconv_kernel<<<(DIMD * HH) / (256 * 4), 256>>>(W);
    q_proj_kernel<<<BB, 256>>>(Qe, W);

    cudaFuncSetAttribute(score_kernel, cudaFuncAttributeMaxDynamicSharedMemorySize,
                         SM_TOTAL);
    score_kernel<<<BB, 512, SM_TOTAL>>>(De, ids, attn, out);
}